// round 15
// baseline (speedup 1.0000x reference)
#include <cuda_runtime.h>
#include <math.h>
#include <stdint.h>

// ---------------- problem constants ----------------
#define BATCH 4
#define NTOK  2048
#define N1    2049          // tokens + cls
#define DIN   768
#define DIM   512
#define H3    1536          // 3*H*DH
#define DEPTH 2
#define ROWS_TOT (BATCH * N1)   // 8196
#define ATT_SCALE 0.125f        // 64^-0.5

// ---------------- scratch (device globals; allocation-free) ----------------
__device__ __align__(256) float g_x  [BATCH * N1 * DIM];
__device__ __align__(256) float g_xn [BATCH * N1 * DIM];
__device__ __align__(256) float g_qkv[BATCH * N1 * H3];
__device__ __align__(256) float g_o  [BATCH * N1 * DIM];
__device__ __align__(256) float g_h  [BATCH * N1 * DIM];

// ---------------- helpers ----------------
__device__ __forceinline__ float gelu_exact(float v) {
    return 0.5f * v * (1.0f + erff(v * 0.70710678118654752440f));
}

// D += A(16x8,row) * B(8x8,col)  tf32 (raw fp32 bits; HW truncates), fp32 accum
__device__ __forceinline__ void mma8(float* c, const uint32_t* a, uint32_t b0, uint32_t b1) {
    asm volatile(
        "mma.sync.aligned.m16n8k8.row.col.f32.tf32.tf32.f32 "
        "{%0,%1,%2,%3}, {%4,%5,%6,%7}, {%8,%9}, {%0,%1,%2,%3};"
        : "+f"(c[0]), "+f"(c[1]), "+f"(c[2]), "+f"(c[3])
        : "r"(a[0]), "r"(a[1]), "r"(a[2]), "r"(a[3]), "r"(b0), "r"(b1));
}

__device__ __forceinline__ uint32_t smem_u32(const void* p) {
    return (uint32_t)__cvta_generic_to_shared(p);
}
// 16B async copy, zero-fill when !pred (src not dereferenced when src-size==0)
__device__ __forceinline__ void cp16(uint32_t dst, const void* src, bool pred) {
    asm volatile("cp.async.cg.shared.global [%0], [%1], 16, %2;"
                 :: "r"(dst), "l"(src), "r"(pred ? 16 : 0));
}
__device__ __forceinline__ void cp_commit() { asm volatile("cp.async.commit_group;"); }
__device__ __forceinline__ void cp_wait0()  { asm volatile("cp.async.wait_group 0;"); }

// ---------------- cls token fill ----------------
__global__ void cls_fill_kernel(const float* __restrict__ cls, float* __restrict__ x) {
    x[(size_t)blockIdx.x * N1 * DIM + threadIdx.x] = cls[threadIdx.x];
}

// ---------------- TF32 tensor-core SGEMM, cp.async double-buffered ----------------
// C[M,N] = A[M,K] @ B[K,N]. mode: 0 none, 1 +bias, 2 gelu(.+bias), 3 +bias+res.
// remap: out row r -> r + r/2048 + 1. Block 128x64x32, 8 warps (4m x 2n) of 32x32.
#define BM 128
#define BN 64
#define BK 32
#define AP 36     // a-frag bank = 4r+j (conflict-free)
#define BP 72     // b-frag bank = 8j+r (conflict-free)
#define SBUF (BM * AP + BK * BP)                 // 6912 floats per buffer
#define GEMM_SMEM (2 * SBUF * 4)                 // 55296 bytes

__global__ __launch_bounds__(256, 3) void sgemm_tf32(
    const float* __restrict__ A, const float* __restrict__ B,
    const float* __restrict__ bias, const float* __restrict__ res,
    float* __restrict__ C, int M, int N, int K, int mode, int remap)
{
    extern __shared__ float gsm[];
    float* As0 = gsm;
    float* Bs0 = gsm + BM * AP;
    float* As1 = gsm + SBUF;
    float* Bs1 = As1 + BM * AP;

    const int tid  = threadIdx.x;
    const int lane = tid & 31;
    const int warp = tid >> 5;
    const int wm   = (warp >> 1) * 32;
    const int wn   = (warp & 1) * 32;
    const int r    = lane >> 2;
    const int j    = lane & 3;
    const int row0 = blockIdx.y * BM;
    const int col0 = blockIdx.x * BN;

    const int a_r = tid >> 3;            // 0..31 (x4 iters of +32)
    const int a_k = (tid & 7) * 4;       // 0..28
    const int b_k = tid >> 4;            // 0..15 (x2 iters of +16)
    const int b_n = (tid & 15) * 4;      // 0..60

    float acc[2][4][4];
#pragma unroll
    for (int mt = 0; mt < 2; mt++)
#pragma unroll
        for (int nt = 0; nt < 4; nt++)
#pragma unroll
            for (int q = 0; q < 4; q++) acc[mt][nt][q] = 0.f;

    // stage tile 0
    {
        float* Ad = As0; float* Bd = Bs0;
#pragma unroll
        for (int i = 0; i < 4; i++) {
            int grow = row0 + i * 32 + a_r;
            cp16(smem_u32(&Ad[(i * 32 + a_r) * AP + a_k]),
                 A + (size_t)(grow < M ? grow : 0) * K + a_k, grow < M);
        }
#pragma unroll
        for (int i = 0; i < 2; i++)
            cp16(smem_u32(&Bd[(i * 16 + b_k) * BP + b_n]),
                 B + (size_t)(i * 16 + b_k) * N + col0 + b_n, true);
        cp_commit();
    }

    const int KB = K / BK;
    for (int kb = 0; kb < KB; kb++) {
        cp_wait0();
        __syncthreads();

        const float* Asp = (kb & 1) ? As1 : As0;
        const float* Bsp = (kb & 1) ? Bs1 : Bs0;

        if (kb + 1 < KB) {
            const int k0 = (kb + 1) * BK;
            float* Ad = (kb & 1) ? As0 : As1;
            float* Bd = (kb & 1) ? Bs0 : Bs1;
#pragma unroll
            for (int i = 0; i < 4; i++) {
                int grow = row0 + i * 32 + a_r;
                cp16(smem_u32(&Ad[(i * 32 + a_r) * AP + a_k]),
                     A + (size_t)(grow < M ? grow : 0) * K + k0 + a_k, grow < M);
            }
#pragma unroll
            for (int i = 0; i < 2; i++)
                cp16(smem_u32(&Bd[(i * 16 + b_k) * BP + b_n]),
                     B + (size_t)(k0 + i * 16 + b_k) * N + col0 + b_n, true);
            cp_commit();
        }

#pragma unroll
        for (int kk = 0; kk < BK; kk += 8) {
            uint32_t af[2][4];
#pragma unroll
            for (int mt = 0; mt < 2; mt++) {
                int mb = wm + mt * 16;
                af[mt][0] = __float_as_uint(Asp[(mb + r    ) * AP + kk + j    ]);
                af[mt][1] = __float_as_uint(Asp[(mb + r + 8) * AP + kk + j    ]);
                af[mt][2] = __float_as_uint(Asp[(mb + r    ) * AP + kk + j + 4]);
                af[mt][3] = __float_as_uint(Asp[(mb + r + 8) * AP + kk + j + 4]);
            }
#pragma unroll
            for (int nt = 0; nt < 4; nt++) {
                uint32_t b0 = __float_as_uint(Bsp[(kk + j    ) * BP + wn + nt * 8 + r]);
                uint32_t b1 = __float_as_uint(Bsp[(kk + j + 4) * BP + wn + nt * 8 + r]);
                mma8(acc[0][nt], af[0], b0, b1);
                mma8(acc[1][nt], af[1], b0, b1);
            }
        }
    }

#pragma unroll
    for (int mt = 0; mt < 2; mt++) {
#pragma unroll
        for (int half = 0; half < 2; half++) {
            int grow = row0 + wm + mt * 16 + r + half * 8;
            if (grow >= M) continue;
            size_t orow = remap ? (size_t)(grow + grow / 2048 + 1) : (size_t)grow;
#pragma unroll
            for (int nt = 0; nt < 4; nt++) {
                int gc = col0 + wn + nt * 8 + 2 * j;
                float v0 = acc[mt][nt][half * 2 + 0];
                float v1 = acc[mt][nt][half * 2 + 1];
                if (mode >= 1) { v0 += bias[gc]; v1 += bias[gc + 1]; }
                if (mode == 2) { v0 = gelu_exact(v0); v1 = gelu_exact(v1); }
                float* cp = C + orow * N + gc;
                if (mode == 3) {
                    const float* rp = res + orow * N + gc;
                    v0 += rp[0]; v1 += rp[1];
                }
                *(float2*)cp = make_float2(v0, v1);
            }
        }
    }
}

// ---------------- LayerNorm (one block per row, D=512) ----------------
__global__ __launch_bounds__(256) void ln_kernel(
    const float* __restrict__ x, const float* __restrict__ g,
    const float* __restrict__ b, float* __restrict__ y)
{
    const int row = blockIdx.x;
    const float* xr = x + (size_t)row * DIM;
    float v[2];
    float s = 0.f, s2 = 0.f;
#pragma unroll
    for (int it = 0; it < 2; it++) {
        v[it] = xr[threadIdx.x + it * 256];
        s += v[it]; s2 += v[it] * v[it];
    }
#pragma unroll
    for (int off = 16; off; off >>= 1) {
        s  += __shfl_xor_sync(0xffffffffu, s,  off);
        s2 += __shfl_xor_sync(0xffffffffu, s2, off);
    }
    __shared__ float rs[8], rs2[8];
    __shared__ float smean, srstd;
    const int w = threadIdx.x >> 5;
    if ((threadIdx.x & 31) == 0) { rs[w] = s; rs2[w] = s2; }
    __syncthreads();
    if (threadIdx.x == 0) {
        float a = 0.f, a2 = 0.f;
        for (int i = 0; i < 8; i++) { a += rs[i]; a2 += rs2[i]; }
        float mean = a * (1.f / DIM);
        float var  = a2 * (1.f / DIM) - mean * mean;
        smean = mean;
        srstd = rsqrtf(var + 1e-5f);
    }
    __syncthreads();
    const float mean = smean, rstd = srstd;
#pragma unroll
    for (int it = 0; it < 2; it++) {
        int c = threadIdx.x + it * 256;
        y[(size_t)row * DIM + c] = (v[it] - mean) * rstd * g[c] + b[c];
    }
}

// ---------------- TF32 flash attention, cp.async double-buffered K/V ----------------
// grid = (17 q-tiles of 128, 8 heads, 4 batch), block 256 (8 warps x 16 q-rows).
// K stored ROW-major [key][d] pitch 68: b-frag bank = 4r+j (conflict-free).
// V row-major [key][d] pitch 72: b-frag bank = 8j+r (conflict-free).
// P never hits smem: c-layout -> a-frag via warp shuffles.
#define ATP 68
#define KSP 68
#define VSP 72
#define NKT 33   // ceil(2049/64)
#define KVBUF (64 * KSP + 64 * VSP)              // per K+V buffer (floats)
#define ATT_SMEM ((128 * ATP + 2 * KVBUF) * 4)   // 106496 bytes

__global__ __launch_bounds__(256, 2) void attn_tf32(
    const float* __restrict__ qkv, const int* __restrict__ lens,
    float* __restrict__ o)
{
    extern __shared__ float sma[];
    float* Qs  = sma;                       // [128][ATP]
    float* Ks0 = Qs + 128 * ATP;            // [64][KSP]
    float* Vs0 = Ks0 + 64 * KSP;            // [64][VSP]
    float* Ks1 = Vs0 + 64 * VSP;
    float* Vs1 = Ks1 + 64 * KSP;

    const int tid  = threadIdx.x;
    const int lane = tid & 31;
    const int warp = tid >> 5;
    const int wq   = warp * 16;
    const int r    = lane >> 2;
    const int j    = lane & 3;

    const int qt = blockIdx.x, h = blockIdx.y, b = blockIdx.z;
    const int qbase = qt * 128;
    const int len1  = lens[b] + 1;
    const float* qkv_b = qkv + (size_t)b * N1 * H3;

    // ---- stage Q tile (plain loads; once per block) ----
#pragma unroll
    for (int i = 0; i < 8; i++) {
        int q  = i * 16 + (tid >> 4);
        int d0 = (tid & 15) * 4;
        int qg = qbase + q;
        float4 v = (qg < N1)
            ? *(const float4*)(qkv_b + (size_t)qg * H3 + h * 64 + d0)
            : make_float4(0.f, 0.f, 0.f, 0.f);
        *(float4*)&Qs[q * ATP + d0] = v;
    }

    const int kv_key = tid >> 4;         // 0..15 (x4 iters of +16)
    const int kv_d0  = (tid & 15) * 4;   // 0..60

    // issue K/V tile kt -> buffer p
    {
        // tile 0 -> buf 0
#pragma unroll
        for (int i = 0; i < 4; i++) {
            int key = i * 16 + kv_key;
            int kg  = key;               // kbase = 0
            bool vd = kg < N1;
            const float* base = qkv_b + (size_t)(vd ? kg : 0) * H3 + h * 64 + kv_d0;
            cp16(smem_u32(&Ks0[key * KSP + kv_d0]), base + 512,  vd);
            cp16(smem_u32(&Vs0[key * VSP + kv_d0]), base + 1024, vd);
        }
        cp_commit();
    }

    const int row0g = qbase + wq + r;
    const int row1g = row0g + 8;
    const bool q0pad = row0g >= len1;
    const bool q1pad = row1g >= len1;
    const int psrc0 = (lane & 28) + (j >> 1);   // shfl source lanes (constant)
    const int psrc1 = psrc0 + 2;
    const bool podd = (j & 1);

    float oacc[8][4];
#pragma unroll
    for (int nt = 0; nt < 8; nt++)
#pragma unroll
        for (int q = 0; q < 4; q++) oacc[nt][q] = 0.f;
    float m0 = -1e30f, m1 = -1e30f, l0 = 0.f, l1 = 0.f;

    for (int kt = 0; kt < NKT; kt++) {
        const int kbase = kt * 64;
        cp_wait0();
        __syncthreads();   // K/V[kt] visible; all prior reads of the other buffer done

        const float* Ksp = (kt & 1) ? Ks1 : Ks0;
        const float* Vsp = (kt & 1) ? Vs1 : Vs0;

        if (kt + 1 < NKT) {
            const int nb = (kt + 1) * 64;
            float* Kd = (kt & 1) ? Ks0 : Ks1;
            float* Vd = (kt & 1) ? Vs0 : Vs1;
#pragma unroll
            for (int i = 0; i < 4; i++) {
                int key = i * 16 + kv_key;
                int kg  = nb + key;
                bool vd = kg < N1;
                const float* base = qkv_b + (size_t)(vd ? kg : 0) * H3 + h * 64 + kv_d0;
                cp16(smem_u32(&Kd[key * KSP + kv_d0]), base + 512,  vd);
                cp16(smem_u32(&Vd[key * VSP + kv_d0]), base + 1024, vd);
            }
            cp_commit();
        }

        // ---- S = Q K^T ----
        float sacc[8][4];
#pragma unroll
        for (int nt = 0; nt < 8; nt++)
#pragma unroll
            for (int q = 0; q < 4; q++) sacc[nt][q] = 0.f;
#pragma unroll
        for (int kk = 0; kk < 64; kk += 8) {
            uint32_t af[4];
            af[0] = __float_as_uint(Qs[(wq + r    ) * ATP + kk + j    ]);
            af[1] = __float_as_uint(Qs[(wq + r + 8) * ATP + kk + j    ]);
            af[2] = __float_as_uint(Qs[(wq + r    ) * ATP + kk + j + 4]);
            af[3] = __float_as_uint(Qs[(wq + r + 8) * ATP + kk + j + 4]);
#pragma unroll
            for (int nt = 0; nt < 8; nt++) {
                uint32_t b0 = __float_as_uint(Ksp[(nt * 8 + r) * KSP + kk + j    ]);
                uint32_t b1 = __float_as_uint(Ksp[(nt * 8 + r) * KSP + kk + j + 4]);
                mma8(sacc[nt], af, b0, b1);
            }
        }

        // ---- scale + mask (fast path when whole tile valid & unmasked) ----
        if (kbase + 64 <= len1) {
#pragma unroll
            for (int nt = 0; nt < 8; nt++)
#pragma unroll
                for (int q = 0; q < 4; q++) sacc[nt][q] *= ATT_SCALE;
        } else {
#pragma unroll
            for (int nt = 0; nt < 8; nt++) {
#pragma unroll
                for (int cc = 0; cc < 2; cc++) {
                    int kg = kbase + nt * 8 + 2 * j + cc;
                    bool kinv = (kg >= N1);
                    bool kpad = (kg >= len1);
                    sacc[nt][cc]     = (kinv || (q0pad && kpad)) ? -1e30f : sacc[nt][cc]     * ATT_SCALE;
                    sacc[nt][2 + cc] = (kinv || (q1pad && kpad)) ? -1e30f : sacc[nt][2 + cc] * ATT_SCALE;
                }
            }
        }

        // ---- online softmax (warp-local, 4-lane row groups) ----
        float mx0 = -1e30f, mx1 = -1e30f;
#pragma unroll
        for (int nt = 0; nt < 8; nt++) {
            mx0 = fmaxf(mx0, fmaxf(sacc[nt][0], sacc[nt][1]));
            mx1 = fmaxf(mx1, fmaxf(sacc[nt][2], sacc[nt][3]));
        }
        mx0 = fmaxf(mx0, __shfl_xor_sync(0xffffffffu, mx0, 1));
        mx0 = fmaxf(mx0, __shfl_xor_sync(0xffffffffu, mx0, 2));
        mx1 = fmaxf(mx1, __shfl_xor_sync(0xffffffffu, mx1, 1));
        mx1 = fmaxf(mx1, __shfl_xor_sync(0xffffffffu, mx1, 2));
        float mn0 = fmaxf(m0, mx0), mn1 = fmaxf(m1, mx1);
        float f0 = __expf(m0 - mn0), f1 = __expf(m1 - mn1);
        m0 = mn0; m1 = mn1;
        float s0 = 0.f, s1 = 0.f;
#pragma unroll
        for (int nt = 0; nt < 8; nt++) {
#pragma unroll
            for (int cc = 0; cc < 2; cc++) {
                float p0 = __expf(sacc[nt][cc]     - m0);
                float p1 = __expf(sacc[nt][2 + cc] - m1);
                sacc[nt][cc] = p0;  sacc[nt][2 + cc] = p1;
                s0 += p0; s1 += p1;
            }
        }
        s0 += __shfl_xor_sync(0xffffffffu, s0, 1);
        s0 += __shfl_xor_sync(0xffffffffu, s0, 2);
        s1 += __shfl_xor_sync(0xffffffffu, s1, 1);
        s1 += __shfl_xor_sync(0xffffffffu, s1, 2);
        l0 = l0 * f0 + s0;
        l1 = l1 * f1 + s1;
#pragma unroll
        for (int nt = 0; nt < 8; nt++) {
            oacc[nt][0] *= f0; oacc[nt][1] *= f0;
            oacc[nt][2] *= f1; oacc[nt][3] *= f1;
        }

        // ---- PV: P a-frags via warp shuffles (no smem round-trip) ----
#pragma unroll
        for (int kk = 0; kk < 64; kk += 8) {
            const int np = kk >> 3;
            float t0 = sacc[np][0], t1 = sacc[np][1];
            float t2 = sacc[np][2], t3 = sacc[np][3];
            float s00 = __shfl_sync(0xffffffffu, t0, psrc0);
            float s10 = __shfl_sync(0xffffffffu, t1, psrc0);
            float s02 = __shfl_sync(0xffffffffu, t2, psrc0);
            float s12 = __shfl_sync(0xffffffffu, t3, psrc0);
            float s01 = __shfl_sync(0xffffffffu, t0, psrc1);
            float s11 = __shfl_sync(0xffffffffu, t1, psrc1);
            float s03 = __shfl_sync(0xffffffffu, t2, psrc1);
            float s13 = __shfl_sync(0xffffffffu, t3, psrc1);
            uint32_t af[4];
            af[0] = __float_as_uint(podd ? s10 : s00);   // P[r   ][kk+j]
            af[1] = __float_as_uint(podd ? s12 : s02);   // P[r+8 ][kk+j]
            af[2] = __float_as_uint(podd ? s11 : s01);   // P[r   ][kk+j+4]
            af[3] = __float_as_uint(podd ? s13 : s03);   // P[r+8 ][kk+j+4]
#pragma unroll
            for (int nt = 0; nt < 8; nt++) {
                uint32_t b0 = __float_as_uint(Vsp[(kk + j    ) * VSP + nt * 8 + r]);
                uint32_t b1 = __float_as_uint(Vsp[(kk + j + 4) * VSP + nt * 8 + r]);
                mma8(oacc[nt], af, b0, b1);
            }
        }
    }

    // ---- normalize + write O ----
    float inv0 = 1.f / l0, inv1 = 1.f / l1;
    float* ob = o + (size_t)b * N1 * DIM + h * 64;
    if (row0g < N1) {
#pragma unroll
        for (int nt = 0; nt < 8; nt++)
            *(float2*)&ob[(size_t)row0g * DIM + nt * 8 + 2 * j] =
                make_float2(oacc[nt][0] * inv0, oacc[nt][1] * inv0);
    }
    if (row1g < N1) {
#pragma unroll
        for (int nt = 0; nt < 8; nt++)
            *(float2*)&ob[(size_t)row1g * DIM + nt * 8 + 2 * j] =
                make_float2(oacc[nt][2] * inv1, oacc[nt][3] * inv1);
    }
}

// ---------------- final LN + classifier head (cls token only) ----------------
__global__ __launch_bounds__(256) void head_kernel(
    const float* __restrict__ x, const float* __restrict__ g,
    const float* __restrict__ bb, const float* __restrict__ hw,
    const float* __restrict__ hb, float* __restrict__ out)
{
    const int b = blockIdx.x;
    const float* xr = x + (size_t)b * N1 * DIM;
    float v[2];
    float s = 0.f, s2 = 0.f;
#pragma unroll
    for (int it = 0; it < 2; it++) {
        v[it] = xr[threadIdx.x + it * 256];
        s += v[it]; s2 += v[it] * v[it];
    }
#pragma unroll
    for (int off = 16; off; off >>= 1) {
        s  += __shfl_xor_sync(0xffffffffu, s,  off);
        s2 += __shfl_xor_sync(0xffffffffu, s2, off);
    }
    __shared__ float rs[8], rs2[8];
    __shared__ float smean, srstd;
    const int w = threadIdx.x >> 5;
    if ((threadIdx.x & 31) == 0) { rs[w] = s; rs2[w] = s2; }
    __syncthreads();
    if (threadIdx.x == 0) {
        float a = 0.f, a2 = 0.f;
        for (int i = 0; i < 8; i++) { a += rs[i]; a2 += rs2[i]; }
        float mean = a * (1.f / DIM);
        float var  = a2 * (1.f / DIM) - mean * mean;
        smean = mean;
        srstd = rsqrtf(var + 1e-5f);
    }
    __syncthreads();
    const float mean = smean, rstd = srstd;

    float d0 = 0.f, d1 = 0.f;
#pragma unroll
    for (int it = 0; it < 2; it++) {
        int c = threadIdx.x + it * 256;
        float xn = (v[it] - mean) * rstd * g[c] + bb[c];
        d0 += xn * hw[2 * c + 0];
        d1 += xn * hw[2 * c + 1];
    }
#pragma unroll
    for (int off = 16; off; off >>= 1) {
        d0 += __shfl_xor_sync(0xffffffffu, d0, off);
        d1 += __shfl_xor_sync(0xffffffffu, d1, off);
    }
    __syncthreads();
    if ((threadIdx.x & 31) == 0) { rs[w] = d0; rs2[w] = d1; }
    __syncthreads();
    if (threadIdx.x == 0) {
        float a0 = 0.f, a1 = 0.f;
        for (int i = 0; i < 8; i++) { a0 += rs[i]; a1 += rs2[i]; }
        out[b * 2 + 0] = a0 + hb[0];
        out[b * 2 + 1] = a1 + hb[1];
    }
}

// ---------------- launch ----------------
extern "C" void kernel_launch(void* const* d_in, const int* in_sizes, int n_in,
                              void* d_out, int out_size)
{
    const float* x      = (const float*)d_in[0];
    const int*   lens   = (const int*)  d_in[1];
    const float* cls    = (const float*)d_in[2];
    const float* fc_w   = (const float*)d_in[3];
    const float* fc_b   = (const float*)d_in[4];
    const float* ln1_g  = (const float*)d_in[5];
    const float* ln1_b  = (const float*)d_in[6];
    const float* qkv_w  = (const float*)d_in[7];
    const float* out_w  = (const float*)d_in[8];
    const float* out_b  = (const float*)d_in[9];
    const float* ln2_g  = (const float*)d_in[10];
    const float* ln2_b  = (const float*)d_in[11];
    const float* ff1_w  = (const float*)d_in[12];
    const float* ff1_b  = (const float*)d_in[13];
    const float* ff2_w  = (const float*)d_in[14];
    const float* ff2_b  = (const float*)d_in[15];
    const float* lnf_g  = (const float*)d_in[16];
    const float* lnf_b  = (const float*)d_in[17];
    const float* head_w = (const float*)d_in[18];
    const float* head_b = (const float*)d_in[19];
    float* out = (float*)d_out;

    float *gx, *gxn, *gqkv, *go, *gh;
    cudaGetSymbolAddress((void**)&gx,   g_x);
    cudaGetSymbolAddress((void**)&gxn,  g_xn);
    cudaGetSymbolAddress((void**)&gqkv, g_qkv);
    cudaGetSymbolAddress((void**)&go,   g_o);
    cudaGetSymbolAddress((void**)&gh,   g_h);

    cudaFuncSetAttribute(sgemm_tf32, cudaFuncAttributeMaxDynamicSharedMemorySize, GEMM_SMEM);
    cudaFuncSetAttribute(attn_tf32,  cudaFuncAttributeMaxDynamicSharedMemorySize, ATT_SMEM);

    // cls rows
    cls_fill_kernel<<<BATCH, DIM>>>(cls, gx);

    // fc + GELU, remapped into cls-offset layout: M=8192, N=512, K=768
    sgemm_tf32<<<dim3(DIM / 64, (BATCH * NTOK + 127) / 128), 256, GEMM_SMEM>>>(
        x, fc_w, fc_b, nullptr, gx, BATCH * NTOK, DIM, DIN, /*mode=*/2, /*remap=*/1);

    const int gy = (ROWS_TOT + 127) / 128;   // 65
    for (int l = 0; l < DEPTH; l++) {
        ln_kernel<<<ROWS_TOT, 256>>>(gx, ln1_g + l * DIM, ln1_b + l * DIM, gxn);
        sgemm_tf32<<<dim3(H3 / 64, gy), 256, GEMM_SMEM>>>(
            gxn, qkv_w + (size_t)l * DIM * H3, nullptr, nullptr, gqkv,
            ROWS_TOT, H3, DIM, 0, 0);
        attn_tf32<<<dim3((N1 + 127) / 128, 8, BATCH), 256, ATT_SMEM>>>(gqkv, lens, go);
        sgemm_tf32<<<dim3(DIM / 64, gy), 256, GEMM_SMEM>>>(
            go, out_w + (size_t)l * DIM * DIM, out_b + l * DIM, gx, gx,
            ROWS_TOT, DIM, DIM, 3, 0);
        ln_kernel<<<ROWS_TOT, 256>>>(gx, ln2_g + l * DIM, ln2_b + l * DIM, gxn);
        sgemm_tf32<<<dim3(DIM / 64, gy), 256, GEMM_SMEM>>>(
            gxn, ff1_w + (size_t)l * DIM * DIM, ff1_b + l * DIM, nullptr, gh,
            ROWS_TOT, DIM, DIM, 2, 0);
        sgemm_tf32<<<dim3(DIM / 64, gy), 256, GEMM_SMEM>>>(
            gh, ff2_w + (size_t)l * DIM * DIM, ff2_b + l * DIM, gx, gx,
            ROWS_TOT, DIM, DIM, 3, 0);
    }

    head_kernel<<<BATCH, 256>>>(gx, lnf_g, lnf_b, head_w, head_b, out);
}

// round 16
// speedup vs baseline: 1.0743x; 1.0743x over previous
#include <cuda_runtime.h>
#include <math.h>
#include <stdint.h>

// ---------------- problem constants ----------------
#define BATCH 4
#define NTOK  2048
#define N1    2049          // tokens + cls
#define DIN   768
#define DIM   512
#define H3    1536          // 3*H*DH
#define DEPTH 2
#define ROWS_TOT (BATCH * N1)   // 8196
#define ATT_SCALE 0.125f        // 64^-0.5
#define ATT_SCALE_LOG2 0.18033688011112042f   // 0.125 * log2(e)

// ---------------- scratch (device globals; allocation-free) ----------------
__device__ __align__(256) float g_x  [BATCH * N1 * DIM];
__device__ __align__(256) float g_xn [BATCH * N1 * DIM];
__device__ __align__(256) float g_qkv[BATCH * N1 * H3];
__device__ __align__(256) float g_o  [BATCH * N1 * DIM];
__device__ __align__(256) float g_h  [BATCH * N1 * DIM];

// ---------------- helpers ----------------
__device__ __forceinline__ float gelu_exact(float v) {
    return 0.5f * v * (1.0f + erff(v * 0.70710678118654752440f));
}

// D += A(16x8,row) * B(8x8,col)  tf32 (raw fp32 bits; HW truncates), fp32 accum
__device__ __forceinline__ void mma8(float* c, const uint32_t* a, uint32_t b0, uint32_t b1) {
    asm volatile(
        "mma.sync.aligned.m16n8k8.row.col.f32.tf32.tf32.f32 "
        "{%0,%1,%2,%3}, {%4,%5,%6,%7}, {%8,%9}, {%0,%1,%2,%3};"
        : "+f"(c[0]), "+f"(c[1]), "+f"(c[2]), "+f"(c[3])
        : "r"(a[0]), "r"(a[1]), "r"(a[2]), "r"(a[3]), "r"(b0), "r"(b1));
}

__device__ __forceinline__ uint32_t smem_u32(const void* p) {
    return (uint32_t)__cvta_generic_to_shared(p);
}
// 16B async copy, zero-fill when !pred
__device__ __forceinline__ void cp16(uint32_t dst, const void* src, bool pred) {
    asm volatile("cp.async.cg.shared.global [%0], [%1], 16, %2;"
                 :: "r"(dst), "l"(src), "r"(pred ? 16 : 0));
}
__device__ __forceinline__ void cp_commit() { asm volatile("cp.async.commit_group;"); }
__device__ __forceinline__ void cp_wait0()  { asm volatile("cp.async.wait_group 0;"); }

// ---------------- cls token fill ----------------
__global__ void cls_fill_kernel(const float* __restrict__ cls, float* __restrict__ x) {
    x[(size_t)blockIdx.x * N1 * DIM + threadIdx.x] = cls[threadIdx.x];
}

// ---------------- TF32 tensor-core SGEMM, 128x128 tile, cp.async dbuf ----------------
// C[M,N] = A[M,K] @ B[K,N]. mode: 0 none, 1 +bias, 2 gelu(.+bias), 3 +bias+res.
// remap: out row r -> r + r/2048 + 1. 8 warps (4m x 2n), warp tile 32x64.
#define BM 128
#define BN 128
#define BK 32
#define AP 36     // a-frag bank = 4r+j (conflict-free)
#define BP 136    // 136 mod 32 = 8 -> b-frag bank = 8j+r (conflict-free)
#define SBUF (BM * AP + BK * BP)                 // 8960 floats per buffer
#define GEMM_SMEM (2 * SBUF * 4)                 // 71680 bytes

__global__ __launch_bounds__(256, 2) void sgemm_tf32(
    const float* __restrict__ A, const float* __restrict__ B,
    const float* __restrict__ bias, const float* __restrict__ res,
    float* __restrict__ C, int M, int N, int K, int mode, int remap)
{
    extern __shared__ float gsm[];
    float* As0 = gsm;
    float* Bs0 = gsm + BM * AP;
    float* As1 = gsm + SBUF;
    float* Bs1 = As1 + BM * AP;

    const int tid  = threadIdx.x;
    const int lane = tid & 31;
    const int warp = tid >> 5;
    const int wm   = (warp >> 1) * 32;   // 0,32,64,96
    const int wn   = (warp & 1) * 64;    // 0,64
    const int r    = lane >> 2;
    const int j    = lane & 3;
    const int row0 = blockIdx.y * BM;
    const int col0 = blockIdx.x * BN;

    const int ld_r = tid >> 3;           // 0..31
    const int ld_c = (tid & 7) * 4;      // 0..28

    float acc[2][8][4];
#pragma unroll
    for (int mt = 0; mt < 2; mt++)
#pragma unroll
        for (int nt = 0; nt < 8; nt++)
#pragma unroll
            for (int q = 0; q < 4; q++) acc[mt][nt][q] = 0.f;

    // stage tile 0
    {
#pragma unroll
        for (int i = 0; i < 4; i++) {
            int grow = row0 + i * 32 + ld_r;
            cp16(smem_u32(&As0[(i * 32 + ld_r) * AP + ld_c]),
                 A + (size_t)(grow < M ? grow : 0) * K + ld_c, grow < M);
        }
#pragma unroll
        for (int i = 0; i < 4; i++)
            cp16(smem_u32(&Bs0[ld_r * BP + ld_c + i * 32]),
                 B + (size_t)ld_r * N + col0 + ld_c + i * 32, true);
        cp_commit();
    }

    const int KB = K / BK;
    for (int kb = 0; kb < KB; kb++) {
        cp_wait0();
        __syncthreads();

        const float* Asp = (kb & 1) ? As1 : As0;
        const float* Bsp = (kb & 1) ? Bs1 : Bs0;

        if (kb + 1 < KB) {
            const int k0 = (kb + 1) * BK;
            float* Ad = (kb & 1) ? As0 : As1;
            float* Bd = (kb & 1) ? Bs0 : Bs1;
#pragma unroll
            for (int i = 0; i < 4; i++) {
                int grow = row0 + i * 32 + ld_r;
                cp16(smem_u32(&Ad[(i * 32 + ld_r) * AP + ld_c]),
                     A + (size_t)(grow < M ? grow : 0) * K + k0 + ld_c, grow < M);
            }
#pragma unroll
            for (int i = 0; i < 4; i++)
                cp16(smem_u32(&Bd[ld_r * BP + ld_c + i * 32]),
                     B + (size_t)(k0 + ld_r) * N + col0 + ld_c + i * 32, true);
            cp_commit();
        }

#pragma unroll
        for (int kk = 0; kk < BK; kk += 8) {
            uint32_t af[2][4];
#pragma unroll
            for (int mt = 0; mt < 2; mt++) {
                int mb = wm + mt * 16;
                af[mt][0] = __float_as_uint(Asp[(mb + r    ) * AP + kk + j    ]);
                af[mt][1] = __float_as_uint(Asp[(mb + r + 8) * AP + kk + j    ]);
                af[mt][2] = __float_as_uint(Asp[(mb + r    ) * AP + kk + j + 4]);
                af[mt][3] = __float_as_uint(Asp[(mb + r + 8) * AP + kk + j + 4]);
            }
#pragma unroll
            for (int nt = 0; nt < 8; nt++) {
                uint32_t b0 = __float_as_uint(Bsp[(kk + j    ) * BP + wn + nt * 8 + r]);
                uint32_t b1 = __float_as_uint(Bsp[(kk + j + 4) * BP + wn + nt * 8 + r]);
                mma8(acc[0][nt], af[0], b0, b1);
                mma8(acc[1][nt], af[1], b0, b1);
            }
        }
    }

#pragma unroll
    for (int mt = 0; mt < 2; mt++) {
#pragma unroll
        for (int half = 0; half < 2; half++) {
            int grow = row0 + wm + mt * 16 + r + half * 8;
            if (grow >= M) continue;
            size_t orow = remap ? (size_t)(grow + grow / 2048 + 1) : (size_t)grow;
#pragma unroll
            for (int nt = 0; nt < 8; nt++) {
                int gc = col0 + wn + nt * 8 + 2 * j;
                float v0 = acc[mt][nt][half * 2 + 0];
                float v1 = acc[mt][nt][half * 2 + 1];
                if (mode >= 1) { v0 += bias[gc]; v1 += bias[gc + 1]; }
                if (mode == 2) { v0 = gelu_exact(v0); v1 = gelu_exact(v1); }
                float* cp = C + orow * N + gc;
                if (mode == 3) {
                    const float* rp = res + orow * N + gc;
                    v0 += rp[0]; v1 += rp[1];
                }
                *(float2*)cp = make_float2(v0, v1);
            }
        }
    }
}

// ---------------- LayerNorm (one block per row, D=512) ----------------
__global__ __launch_bounds__(256) void ln_kernel(
    const float* __restrict__ x, const float* __restrict__ g,
    const float* __restrict__ b, float* __restrict__ y)
{
    const int row = blockIdx.x;
    const float* xr = x + (size_t)row * DIM;
    float v[2];
    float s = 0.f, s2 = 0.f;
#pragma unroll
    for (int it = 0; it < 2; it++) {
        v[it] = xr[threadIdx.x + it * 256];
        s += v[it]; s2 += v[it] * v[it];
    }
#pragma unroll
    for (int off = 16; off; off >>= 1) {
        s  += __shfl_xor_sync(0xffffffffu, s,  off);
        s2 += __shfl_xor_sync(0xffffffffu, s2, off);
    }
    __shared__ float rs[8], rs2[8];
    __shared__ float smean, srstd;
    const int w = threadIdx.x >> 5;
    if ((threadIdx.x & 31) == 0) { rs[w] = s; rs2[w] = s2; }
    __syncthreads();
    if (threadIdx.x == 0) {
        float a = 0.f, a2 = 0.f;
        for (int i = 0; i < 8; i++) { a += rs[i]; a2 += rs2[i]; }
        float mean = a * (1.f / DIM);
        float var  = a2 * (1.f / DIM) - mean * mean;
        smean = mean;
        srstd = rsqrtf(var + 1e-5f);
    }
    __syncthreads();
    const float mean = smean, rstd = srstd;
#pragma unroll
    for (int it = 0; it < 2; it++) {
        int c = threadIdx.x + it * 256;
        y[(size_t)row * DIM + c] = (v[it] - mean) * rstd * g[c] + b[c];
    }
}

// ---------------- TF32 flash attention, cp.async double-buffered K/V ----------------
// grid = (17 q-tiles of 128, 8 heads, 4 batch), block 256 (8 warps x 16 q-rows).
// Base-2 softmax: scale = ATT_SCALE*log2(e), exp2f throughout (same math).
#define ATP 68
#define KSP 68
#define VSP 72
#define NKT 33   // ceil(2049/64)
#define KVBUF (64 * KSP + 64 * VSP)
#define ATT_SMEM ((128 * ATP + 2 * KVBUF) * 4)   // 106496 bytes

__global__ __launch_bounds__(256, 2) void attn_tf32(
    const float* __restrict__ qkv, const int* __restrict__ lens,
    float* __restrict__ o)
{
    extern __shared__ float sma[];
    float* Qs  = sma;                       // [128][ATP]
    float* Ks0 = Qs + 128 * ATP;            // [64][KSP]
    float* Vs0 = Ks0 + 64 * KSP;            // [64][VSP]
    float* Ks1 = Vs0 + 64 * VSP;
    float* Vs1 = Ks1 + 64 * KSP;

    const int tid  = threadIdx.x;
    const int lane = tid & 31;
    const int warp = tid >> 5;
    const int wq   = warp * 16;
    const int r    = lane >> 2;
    const int j    = lane & 3;

    const int qt = blockIdx.x, h = blockIdx.y, b = blockIdx.z;
    const int qbase = qt * 128;
    const int len1  = lens[b] + 1;
    const float* qkv_b = qkv + (size_t)b * N1 * H3;

    // ---- stage Q tile ----
#pragma unroll
    for (int i = 0; i < 8; i++) {
        int q  = i * 16 + (tid >> 4);
        int d0 = (tid & 15) * 4;
        int qg = qbase + q;
        float4 v = (qg < N1)
            ? *(const float4*)(qkv_b + (size_t)qg * H3 + h * 64 + d0)
            : make_float4(0.f, 0.f, 0.f, 0.f);
        *(float4*)&Qs[q * ATP + d0] = v;
    }

    const int kv_key = tid >> 4;         // 0..15 (x4 iters of +16)
    const int kv_d0  = (tid & 15) * 4;   // 0..60

    {   // tile 0 -> buf 0
#pragma unroll
        for (int i = 0; i < 4; i++) {
            int key = i * 16 + kv_key;
            bool vd = key < N1;
            const float* base = qkv_b + (size_t)(vd ? key : 0) * H3 + h * 64 + kv_d0;
            cp16(smem_u32(&Ks0[key * KSP + kv_d0]), base + 512,  vd);
            cp16(smem_u32(&Vs0[key * VSP + kv_d0]), base + 1024, vd);
        }
        cp_commit();
    }

    const int row0g = qbase + wq + r;
    const int row1g = row0g + 8;
    const bool q0pad = row0g >= len1;
    const bool q1pad = row1g >= len1;
    const int psrc0 = (lane & 28) + (j >> 1);
    const int psrc1 = psrc0 + 2;
    const bool podd = (j & 1);

    float oacc[8][4];
#pragma unroll
    for (int nt = 0; nt < 8; nt++)
#pragma unroll
        for (int q = 0; q < 4; q++) oacc[nt][q] = 0.f;
    float m0 = -1e30f, m1 = -1e30f, l0 = 0.f, l1 = 0.f;

    for (int kt = 0; kt < NKT; kt++) {
        const int kbase = kt * 64;
        cp_wait0();
        __syncthreads();

        const float* Ksp = (kt & 1) ? Ks1 : Ks0;
        const float* Vsp = (kt & 1) ? Vs1 : Vs0;

        if (kt + 1 < NKT) {
            const int nb = (kt + 1) * 64;
            float* Kd = (kt & 1) ? Ks0 : Ks1;
            float* Vd = (kt & 1) ? Vs0 : Vs1;
#pragma unroll
            for (int i = 0; i < 4; i++) {
                int key = i * 16 + kv_key;
                int kg  = nb + key;
                bool vd = kg < N1;
                const float* base = qkv_b + (size_t)(vd ? kg : 0) * H3 + h * 64 + kv_d0;
                cp16(smem_u32(&Kd[key * KSP + kv_d0]), base + 512,  vd);
                cp16(smem_u32(&Vd[key * VSP + kv_d0]), base + 1024, vd);
            }
            cp_commit();
        }

        // ---- S = Q K^T ----
        float sacc[8][4];
#pragma unroll
        for (int nt = 0; nt < 8; nt++)
#pragma unroll
            for (int q = 0; q < 4; q++) sacc[nt][q] = 0.f;
#pragma unroll
        for (int kk = 0; kk < 64; kk += 8) {
            uint32_t af[4];
            af[0] = __float_as_uint(Qs[(wq + r    ) * ATP + kk + j    ]);
            af[1] = __float_as_uint(Qs[(wq + r + 8) * ATP + kk + j    ]);
            af[2] = __float_as_uint(Qs[(wq + r    ) * ATP + kk + j + 4]);
            af[3] = __float_as_uint(Qs[(wq + r + 8) * ATP + kk + j + 4]);
#pragma unroll
            for (int nt = 0; nt < 8; nt++) {
                uint32_t b0 = __float_as_uint(Ksp[(nt * 8 + r) * KSP + kk + j    ]);
                uint32_t b1 = __float_as_uint(Ksp[(nt * 8 + r) * KSP + kk + j + 4]);
                mma8(sacc[nt], af, b0, b1);
            }
        }

        // ---- scale (base-2) + mask ----
        if (kbase + 64 <= len1) {
#pragma unroll
            for (int nt = 0; nt < 8; nt++)
#pragma unroll
                for (int q = 0; q < 4; q++) sacc[nt][q] *= ATT_SCALE_LOG2;
        } else {
#pragma unroll
            for (int nt = 0; nt < 8; nt++) {
#pragma unroll
                for (int cc = 0; cc < 2; cc++) {
                    int kg = kbase + nt * 8 + 2 * j + cc;
                    bool kinv = (kg >= N1);
                    bool kpad = (kg >= len1);
                    sacc[nt][cc]     = (kinv || (q0pad && kpad)) ? -1e30f : sacc[nt][cc]     * ATT_SCALE_LOG2;
                    sacc[nt][2 + cc] = (kinv || (q1pad && kpad)) ? -1e30f : sacc[nt][2 + cc] * ATT_SCALE_LOG2;
                }
            }
        }

        // ---- online softmax (base-2, warp-local) ----
        float mx0 = -1e30f, mx1 = -1e30f;
#pragma unroll
        for (int nt = 0; nt < 8; nt++) {
            mx0 = fmaxf(mx0, fmaxf(sacc[nt][0], sacc[nt][1]));
            mx1 = fmaxf(mx1, fmaxf(sacc[nt][2], sacc[nt][3]));
        }
        mx0 = fmaxf(mx0, __shfl_xor_sync(0xffffffffu, mx0, 1));
        mx0 = fmaxf(mx0, __shfl_xor_sync(0xffffffffu, mx0, 2));
        mx1 = fmaxf(mx1, __shfl_xor_sync(0xffffffffu, mx1, 1));
        mx1 = fmaxf(mx1, __shfl_xor_sync(0xffffffffu, mx1, 2));
        float mn0 = fmaxf(m0, mx0), mn1 = fmaxf(m1, mx1);
        float f0 = exp2f(m0 - mn0), f1 = exp2f(m1 - mn1);
        m0 = mn0; m1 = mn1;
        float s0 = 0.f, s1 = 0.f;
#pragma unroll
        for (int nt = 0; nt < 8; nt++) {
#pragma unroll
            for (int cc = 0; cc < 2; cc++) {
                float p0 = exp2f(sacc[nt][cc]     - m0);
                float p1 = exp2f(sacc[nt][2 + cc] - m1);
                sacc[nt][cc] = p0;  sacc[nt][2 + cc] = p1;
                s0 += p0; s1 += p1;
            }
        }
        s0 += __shfl_xor_sync(0xffffffffu, s0, 1);
        s0 += __shfl_xor_sync(0xffffffffu, s0, 2);
        s1 += __shfl_xor_sync(0xffffffffu, s1, 1);
        s1 += __shfl_xor_sync(0xffffffffu, s1, 2);
        l0 = l0 * f0 + s0;
        l1 = l1 * f1 + s1;
#pragma unroll
        for (int nt = 0; nt < 8; nt++) {
            oacc[nt][0] *= f0; oacc[nt][1] *= f0;
            oacc[nt][2] *= f1; oacc[nt][3] *= f1;
        }

        // ---- PV: P a-frags via warp shuffles ----
#pragma unroll
        for (int kk = 0; kk < 64; kk += 8) {
            const int np = kk >> 3;
            float t0 = sacc[np][0], t1 = sacc[np][1];
            float t2 = sacc[np][2], t3 = sacc[np][3];
            float s00 = __shfl_sync(0xffffffffu, t0, psrc0);
            float s10 = __shfl_sync(0xffffffffu, t1, psrc0);
            float s02 = __shfl_sync(0xffffffffu, t2, psrc0);
            float s12 = __shfl_sync(0xffffffffu, t3, psrc0);
            float s01 = __shfl_sync(0xffffffffu, t0, psrc1);
            float s11 = __shfl_sync(0xffffffffu, t1, psrc1);
            float s03 = __shfl_sync(0xffffffffu, t2, psrc1);
            float s13 = __shfl_sync(0xffffffffu, t3, psrc1);
            uint32_t af[4];
            af[0] = __float_as_uint(podd ? s10 : s00);
            af[1] = __float_as_uint(podd ? s12 : s02);
            af[2] = __float_as_uint(podd ? s11 : s01);
            af[3] = __float_as_uint(podd ? s13 : s03);
#pragma unroll
            for (int nt = 0; nt < 8; nt++) {
                uint32_t b0 = __float_as_uint(Vsp[(kk + j    ) * VSP + nt * 8 + r]);
                uint32_t b1 = __float_as_uint(Vsp[(kk + j + 4) * VSP + nt * 8 + r]);
                mma8(oacc[nt], af, b0, b1);
            }
        }
    }

    // ---- normalize + write O ----
    float inv0 = 1.f / l0, inv1 = 1.f / l1;
    float* ob = o + (size_t)b * N1 * DIM + h * 64;
    if (row0g < N1) {
#pragma unroll
        for (int nt = 0; nt < 8; nt++)
            *(float2*)&ob[(size_t)row0g * DIM + nt * 8 + 2 * j] =
                make_float2(oacc[nt][0] * inv0, oacc[nt][1] * inv0);
    }
    if (row1g < N1) {
#pragma unroll
        for (int nt = 0; nt < 8; nt++)
            *(float2*)&ob[(size_t)row1g * DIM + nt * 8 + 2 * j] =
                make_float2(oacc[nt][2] * inv1, oacc[nt][3] * inv1);
    }
}

// ---------------- final LN + classifier head (cls token only) ----------------
__global__ __launch_bounds__(256) void head_kernel(
    const float* __restrict__ x, const float* __restrict__ g,
    const float* __restrict__ bb, const float* __restrict__ hw,
    const float* __restrict__ hb, float* __restrict__ out)
{
    const int b = blockIdx.x;
    const float* xr = x + (size_t)b * N1 * DIM;
    float v[2];
    float s = 0.f, s2 = 0.f;
#pragma unroll
    for (int it = 0; it < 2; it++) {
        v[it] = xr[threadIdx.x + it * 256];
        s += v[it]; s2 += v[it] * v[it];
    }
#pragma unroll
    for (int off = 16; off; off >>= 1) {
        s  += __shfl_xor_sync(0xffffffffu, s,  off);
        s2 += __shfl_xor_sync(0xffffffffu, s2, off);
    }
    __shared__ float rs[8], rs2[8];
    __shared__ float smean, srstd;
    const int w = threadIdx.x >> 5;
    if ((threadIdx.x & 31) == 0) { rs[w] = s; rs2[w] = s2; }
    __syncthreads();
    if (threadIdx.x == 0) {
        float a = 0.f, a2 = 0.f;
        for (int i = 0; i < 8; i++) { a += rs[i]; a2 += rs2[i]; }
        float mean = a * (1.f / DIM);
        float var  = a2 * (1.f / DIM) - mean * mean;
        smean = mean;
        srstd = rsqrtf(var + 1e-5f);
    }
    __syncthreads();
    const float mean = smean, rstd = srstd;

    float d0 = 0.f, d1 = 0.f;
#pragma unroll
    for (int it = 0; it < 2; it++) {
        int c = threadIdx.x + it * 256;
        float xn = (v[it] - mean) * rstd * g[c] + bb[c];
        d0 += xn * hw[2 * c + 0];
        d1 += xn * hw[2 * c + 1];
    }
#pragma unroll
    for (int off = 16; off; off >>= 1) {
        d0 += __shfl_xor_sync(0xffffffffu, d0, off);
        d1 += __shfl_xor_sync(0xffffffffu, d1, off);
    }
    __syncthreads();
    if ((threadIdx.x & 31) == 0) { rs[w] = d0; rs2[w] = d1; }
    __syncthreads();
    if (threadIdx.x == 0) {
        float a0 = 0.f, a1 = 0.f;
        for (int i = 0; i < 8; i++) { a0 += rs[i]; a1 += rs2[i]; }
        out[b * 2 + 0] = a0 + hb[0];
        out[b * 2 + 1] = a1 + hb[1];
    }
}

// ---------------- launch ----------------
extern "C" void kernel_launch(void* const* d_in, const int* in_sizes, int n_in,
                              void* d_out, int out_size)
{
    const float* x      = (const float*)d_in[0];
    const int*   lens   = (const int*)  d_in[1];
    const float* cls    = (const float*)d_in[2];
    const float* fc_w   = (const float*)d_in[3];
    const float* fc_b   = (const float*)d_in[4];
    const float* ln1_g  = (const float*)d_in[5];
    const float* ln1_b  = (const float*)d_in[6];
    const float* qkv_w  = (const float*)d_in[7];
    const float* out_w  = (const float*)d_in[8];
    const float* out_b  = (const float*)d_in[9];
    const float* ln2_g  = (const float*)d_in[10];
    const float* ln2_b  = (const float*)d_in[11];
    const float* ff1_w  = (const float*)d_in[12];
    const float* ff1_b  = (const float*)d_in[13];
    const float* ff2_w  = (const float*)d_in[14];
    const float* ff2_b  = (const float*)d_in[15];
    const float* lnf_g  = (const float*)d_in[16];
    const float* lnf_b  = (const float*)d_in[17];
    const float* head_w = (const float*)d_in[18];
    const float* head_b = (const float*)d_in[19];
    float* out = (float*)d_out;

    float *gx, *gxn, *gqkv, *go, *gh;
    cudaGetSymbolAddress((void**)&gx,   g_x);
    cudaGetSymbolAddress((void**)&gxn,  g_xn);
    cudaGetSymbolAddress((void**)&gqkv, g_qkv);
    cudaGetSymbolAddress((void**)&go,   g_o);
    cudaGetSymbolAddress((void**)&gh,   g_h);

    cudaFuncSetAttribute(sgemm_tf32, cudaFuncAttributeMaxDynamicSharedMemorySize, GEMM_SMEM);
    cudaFuncSetAttribute(attn_tf32,  cudaFuncAttributeMaxDynamicSharedMemorySize, ATT_SMEM);

    // cls rows
    cls_fill_kernel<<<BATCH, DIM>>>(cls, gx);

    // fc + GELU, remapped into cls-offset layout: M=8192, N=512, K=768
    sgemm_tf32<<<dim3(DIM / BN, (BATCH * NTOK + BM - 1) / BM), 256, GEMM_SMEM>>>(
        x, fc_w, fc_b, nullptr, gx, BATCH * NTOK, DIM, DIN, /*mode=*/2, /*remap=*/1);

    const int gy = (ROWS_TOT + BM - 1) / BM;   // 65
    for (int l = 0; l < DEPTH; l++) {
        ln_kernel<<<ROWS_TOT, 256>>>(gx, ln1_g + l * DIM, ln1_b + l * DIM, gxn);
        sgemm_tf32<<<dim3(H3 / BN, gy), 256, GEMM_SMEM>>>(
            gxn, qkv_w + (size_t)l * DIM * H3, nullptr, nullptr, gqkv,
            ROWS_TOT, H3, DIM, 0, 0);
        attn_tf32<<<dim3((N1 + 127) / 128, 8, BATCH), 256, ATT_SMEM>>>(gqkv, lens, go);
        sgemm_tf32<<<dim3(DIM / BN, gy), 256, GEMM_SMEM>>>(
            go, out_w + (size_t)l * DIM * DIM, out_b + l * DIM, gx, gx,
            ROWS_TOT, DIM, DIM, 3, 0);
        ln_kernel<<<ROWS_TOT, 256>>>(gx, ln2_g + l * DIM, ln2_b + l * DIM, gxn);
        sgemm_tf32<<<dim3(DIM / BN, gy), 256, GEMM_SMEM>>>(
            gxn, ff1_w + (size_t)l * DIM * DIM, ff1_b + l * DIM, nullptr, gh,
            ROWS_TOT, DIM, DIM, 2, 0);
        sgemm_tf32<<<dim3(DIM / BN, gy), 256, GEMM_SMEM>>>(
            gh, ff2_w + (size_t)l * DIM * DIM, ff2_b + l * DIM, gx, gx,
            ROWS_TOT, DIM, DIM, 3, 0);
    }

    head_kernel<<<BATCH, 256>>>(gx, lnf_g, lnf_b, head_w, head_b, out);
}

// round 17
// speedup vs baseline: 1.1443x; 1.0651x over previous
#include <cuda_runtime.h>
#include <math.h>
#include <stdint.h>

// ---------------- problem constants ----------------
#define BATCH 4
#define NTOK  2048
#define N1    2049          // tokens + cls
#define DIN   768
#define DIM   512
#define H3    1536          // 3*H*DH
#define DEPTH 2
#define ROWS_TOT (BATCH * N1)   // 8196
#define ATT_SCALE_LOG2 0.18033688011112042f   // 0.125 * log2(e)

// ---------------- scratch (device globals; allocation-free) ----------------
__device__ __align__(256) float g_x  [BATCH * N1 * DIM];
__device__ __align__(256) float g_xn [BATCH * N1 * DIM];
__device__ __align__(256) float g_qkv[BATCH * N1 * H3];
__device__ __align__(256) float g_o  [BATCH * N1 * DIM];
__device__ __align__(256) float g_h  [BATCH * N1 * DIM];

// ---------------- helpers ----------------
__device__ __forceinline__ float gelu_exact(float v) {
    return 0.5f * v * (1.0f + erff(v * 0.70710678118654752440f));
}

// D += A(16x8,row) * B(8x8,col)  tf32 (raw fp32 bits; HW truncates), fp32 accum
__device__ __forceinline__ void mma8(float* c, const uint32_t* a, uint32_t b0, uint32_t b1) {
    asm volatile(
        "mma.sync.aligned.m16n8k8.row.col.f32.tf32.tf32.f32 "
        "{%0,%1,%2,%3}, {%4,%5,%6,%7}, {%8,%9}, {%0,%1,%2,%3};"
        : "+f"(c[0]), "+f"(c[1]), "+f"(c[2]), "+f"(c[3])
        : "r"(a[0]), "r"(a[1]), "r"(a[2]), "r"(a[3]), "r"(b0), "r"(b1));
}

__device__ __forceinline__ uint32_t smem_u32(const void* p) {
    return (uint32_t)__cvta_generic_to_shared(p);
}
// 16B async copy, zero-fill when !pred
__device__ __forceinline__ void cp16(uint32_t dst, const void* src, bool pred) {
    asm volatile("cp.async.cg.shared.global [%0], [%1], 16, %2;"
                 :: "r"(dst), "l"(src), "r"(pred ? 16 : 0));
}
__device__ __forceinline__ void cp_commit() { asm volatile("cp.async.commit_group;"); }
__device__ __forceinline__ void cp_wait0()  { asm volatile("cp.async.wait_group 0;"); }

// ---------------- cls token fill ----------------
__global__ void cls_fill_kernel(const float* __restrict__ cls, float* __restrict__ x) {
    x[(size_t)blockIdx.x * N1 * DIM + threadIdx.x] = cls[threadIdx.x];
}

// ---------------- TF32 tensor-core SGEMM, 128x128 tile, cp.async dbuf ----------------
#define BM 128
#define BN 128
#define BK 32
#define AP 36     // a-frag bank = 4r+j (conflict-free)
#define BP 136    // 136 mod 32 = 8 -> b-frag bank = 8j+r (conflict-free)
#define SBUF (BM * AP + BK * BP)
#define GEMM_SMEM (2 * SBUF * 4)                 // 71680 bytes

__global__ __launch_bounds__(256, 2) void sgemm_tf32(
    const float* __restrict__ A, const float* __restrict__ B,
    const float* __restrict__ bias, const float* __restrict__ res,
    float* __restrict__ C, int M, int N, int K, int mode, int remap)
{
    extern __shared__ float gsm[];
    float* As0 = gsm;
    float* Bs0 = gsm + BM * AP;
    float* As1 = gsm + SBUF;
    float* Bs1 = As1 + BM * AP;

    const int tid  = threadIdx.x;
    const int lane = tid & 31;
    const int warp = tid >> 5;
    const int wm   = (warp >> 1) * 32;
    const int wn   = (warp & 1) * 64;
    const int r    = lane >> 2;
    const int j    = lane & 3;
    const int row0 = blockIdx.y * BM;
    const int col0 = blockIdx.x * BN;

    const int ld_r = tid >> 3;
    const int ld_c = (tid & 7) * 4;

    float acc[2][8][4];
#pragma unroll
    for (int mt = 0; mt < 2; mt++)
#pragma unroll
        for (int nt = 0; nt < 8; nt++)
#pragma unroll
            for (int q = 0; q < 4; q++) acc[mt][nt][q] = 0.f;

    {
#pragma unroll
        for (int i = 0; i < 4; i++) {
            int grow = row0 + i * 32 + ld_r;
            cp16(smem_u32(&As0[(i * 32 + ld_r) * AP + ld_c]),
                 A + (size_t)(grow < M ? grow : 0) * K + ld_c, grow < M);
        }
#pragma unroll
        for (int i = 0; i < 4; i++)
            cp16(smem_u32(&Bs0[ld_r * BP + ld_c + i * 32]),
                 B + (size_t)ld_r * N + col0 + ld_c + i * 32, true);
        cp_commit();
    }

    const int KB = K / BK;
    for (int kb = 0; kb < KB; kb++) {
        cp_wait0();
        __syncthreads();

        const float* Asp = (kb & 1) ? As1 : As0;
        const float* Bsp = (kb & 1) ? Bs1 : Bs0;

        if (kb + 1 < KB) {
            const int k0 = (kb + 1) * BK;
            float* Ad = (kb & 1) ? As0 : As1;
            float* Bd = (kb & 1) ? Bs0 : Bs1;
#pragma unroll
            for (int i = 0; i < 4; i++) {
                int grow = row0 + i * 32 + ld_r;
                cp16(smem_u32(&Ad[(i * 32 + ld_r) * AP + ld_c]),
                     A + (size_t)(grow < M ? grow : 0) * K + k0 + ld_c, grow < M);
            }
#pragma unroll
            for (int i = 0; i < 4; i++)
                cp16(smem_u32(&Bd[ld_r * BP + ld_c + i * 32]),
                     B + (size_t)(k0 + ld_r) * N + col0 + ld_c + i * 32, true);
            cp_commit();
        }

#pragma unroll
        for (int kk = 0; kk < BK; kk += 8) {
            uint32_t af[2][4];
#pragma unroll
            for (int mt = 0; mt < 2; mt++) {
                int mb = wm + mt * 16;
                af[mt][0] = __float_as_uint(Asp[(mb + r    ) * AP + kk + j    ]);
                af[mt][1] = __float_as_uint(Asp[(mb + r + 8) * AP + kk + j    ]);
                af[mt][2] = __float_as_uint(Asp[(mb + r    ) * AP + kk + j + 4]);
                af[mt][3] = __float_as_uint(Asp[(mb + r + 8) * AP + kk + j + 4]);
            }
#pragma unroll
            for (int nt = 0; nt < 8; nt++) {
                uint32_t b0 = __float_as_uint(Bsp[(kk + j    ) * BP + wn + nt * 8 + r]);
                uint32_t b1 = __float_as_uint(Bsp[(kk + j + 4) * BP + wn + nt * 8 + r]);
                mma8(acc[0][nt], af[0], b0, b1);
                mma8(acc[1][nt], af[1], b0, b1);
            }
        }
    }

#pragma unroll
    for (int mt = 0; mt < 2; mt++) {
#pragma unroll
        for (int half = 0; half < 2; half++) {
            int grow = row0 + wm + mt * 16 + r + half * 8;
            if (grow >= M) continue;
            size_t orow = remap ? (size_t)(grow + grow / 2048 + 1) : (size_t)grow;
#pragma unroll
            for (int nt = 0; nt < 8; nt++) {
                int gc = col0 + wn + nt * 8 + 2 * j;
                float v0 = acc[mt][nt][half * 2 + 0];
                float v1 = acc[mt][nt][half * 2 + 1];
                if (mode >= 1) { v0 += bias[gc]; v1 += bias[gc + 1]; }
                if (mode == 2) { v0 = gelu_exact(v0); v1 = gelu_exact(v1); }
                float* cp = C + orow * N + gc;
                if (mode == 3) {
                    const float* rp = res + orow * N + gc;
                    v0 += rp[0]; v1 += rp[1];
                }
                *(float2*)cp = make_float2(v0, v1);
            }
        }
    }
}

// ---------------- LayerNorm (one block per row, D=512) ----------------
__global__ __launch_bounds__(256) void ln_kernel(
    const float* __restrict__ x, const float* __restrict__ g,
    const float* __restrict__ b, float* __restrict__ y)
{
    const int row = blockIdx.x;
    const float* xr = x + (size_t)row * DIM;
    float v[2];
    float s = 0.f, s2 = 0.f;
#pragma unroll
    for (int it = 0; it < 2; it++) {
        v[it] = xr[threadIdx.x + it * 256];
        s += v[it]; s2 += v[it] * v[it];
    }
#pragma unroll
    for (int off = 16; off; off >>= 1) {
        s  += __shfl_xor_sync(0xffffffffu, s,  off);
        s2 += __shfl_xor_sync(0xffffffffu, s2, off);
    }
    __shared__ float rs[8], rs2[8];
    __shared__ float smean, srstd;
    const int w = threadIdx.x >> 5;
    if ((threadIdx.x & 31) == 0) { rs[w] = s; rs2[w] = s2; }
    __syncthreads();
    if (threadIdx.x == 0) {
        float a = 0.f, a2 = 0.f;
        for (int i = 0; i < 8; i++) { a += rs[i]; a2 += rs2[i]; }
        float mean = a * (1.f / DIM);
        float var  = a2 * (1.f / DIM) - mean * mean;
        smean = mean;
        srstd = rsqrtf(var + 1e-5f);
    }
    __syncthreads();
    const float mean = smean, rstd = srstd;
#pragma unroll
    for (int it = 0; it < 2; it++) {
        int c = threadIdx.x + it * 256;
        y[(size_t)row * DIM + c] = (v[it] - mean) * rstd * g[c] + b[c];
    }
}

// ---------------- TF32 flash attention v2 ----------------
// 128 threads (4 warps), warp owns 32 q-rows (2 m-tiles). Q lives in register
// a-fragments (loaded once). P round-trips through smem (Q staging region,
// reused). K/V cp.async double-buffered. Base-2 online softmax.
#define ATP 68
#define KSP 68
#define VSP 72
#define NKT 33   // ceil(2049/64)
#define ATT_SMEM ((128 * ATP + 2 * (64 * KSP + 64 * VSP)) * 4)   // 106496 bytes

__global__ __launch_bounds__(128, 2) void attn_tf32(
    const float* __restrict__ qkv, const int* __restrict__ lens,
    float* __restrict__ o)
{
    extern __shared__ float sma[];
    float* Ps  = sma;                       // [128][ATP]  (Q staging, then P)
    float* Ks0 = Ps + 128 * ATP;            // [64][KSP]
    float* Vs0 = Ks0 + 64 * KSP;            // [64][VSP]
    float* Ks1 = Vs0 + 64 * VSP;
    float* Vs1 = Ks1 + 64 * KSP;

    const int tid  = threadIdx.x;
    const int lane = tid & 31;
    const int warp = tid >> 5;
    const int wq   = warp * 32;
    const int r    = lane >> 2;
    const int j    = lane & 3;

    const int qt = blockIdx.x, h = blockIdx.y, b = blockIdx.z;
    const int qbase = qt * 128;
    const int len1  = lens[b] + 1;
    const float* qkv_b = qkv + (size_t)b * N1 * H3;

    const int kv_key = tid >> 4;         // 0..7 (x8 iters of +8)
    const int kv_d0  = (tid & 15) * 4;   // 0..60

    // ---- issue K/V tile 0 (cp.async) first, overlap with Q staging ----
#pragma unroll
    for (int i = 0; i < 8; i++) {
        int key = i * 8 + kv_key;
        bool vd = key < N1;
        const float* base = qkv_b + (size_t)(vd ? key : 0) * H3 + h * 64 + kv_d0;
        cp16(smem_u32(&Ks0[key * KSP + kv_d0]), base + 512,  vd);
        cp16(smem_u32(&Vs0[key * VSP + kv_d0]), base + 1024, vd);
    }
    cp_commit();

    // ---- stage Q tile into Ps ----
#pragma unroll
    for (int i = 0; i < 16; i++) {
        int q  = i * 8 + (tid >> 4);
        int d0 = (tid & 15) * 4;
        int qg = qbase + q;
        float4 v = (qg < N1)
            ? *(const float4*)(qkv_b + (size_t)qg * H3 + h * 64 + d0)
            : make_float4(0.f, 0.f, 0.f, 0.f);
        *(float4*)&Ps[q * ATP + d0] = v;
    }
    __syncthreads();

    // ---- extract Q a-fragments (held in registers for the whole kernel) ----
    uint32_t Qf[2][8][4];
#pragma unroll
    for (int mt = 0; mt < 2; mt++) {
        const int brow = wq + mt * 16;
#pragma unroll
        for (int kk = 0; kk < 8; kk++) {
            Qf[mt][kk][0] = __float_as_uint(Ps[(brow + r    ) * ATP + kk * 8 + j    ]);
            Qf[mt][kk][1] = __float_as_uint(Ps[(brow + r + 8) * ATP + kk * 8 + j    ]);
            Qf[mt][kk][2] = __float_as_uint(Ps[(brow + r    ) * ATP + kk * 8 + j + 4]);
            Qf[mt][kk][3] = __float_as_uint(Ps[(brow + r + 8) * ATP + kk * 8 + j + 4]);
        }
    }
    // Ps rows [wq, wq+32) now owned exclusively by this warp (P scratch).

    // global rows handled by this lane: wq + r + {0,8,16,24}
    int rowg[4];
    bool qpad[4];
#pragma unroll
    for (int q = 0; q < 4; q++) {
        rowg[q] = qbase + wq + (q >> 1) * 16 + (q & 1) * 8 + r;
        qpad[q] = rowg[q] >= len1;
    }

    float oacc[2][8][4];
#pragma unroll
    for (int mt = 0; mt < 2; mt++)
#pragma unroll
        for (int nt = 0; nt < 8; nt++)
#pragma unroll
            for (int q = 0; q < 4; q++) oacc[mt][nt][q] = 0.f;
    float m[4] = {-1e30f, -1e30f, -1e30f, -1e30f};
    float l[4] = {0.f, 0.f, 0.f, 0.f};

    for (int kt = 0; kt < NKT; kt++) {
        const int kbase = kt * 64;
        cp_wait0();
        __syncthreads();

        const float* Ksp = (kt & 1) ? Ks1 : Ks0;
        const float* Vsp = (kt & 1) ? Vs1 : Vs0;

        if (kt + 1 < NKT) {
            const int nb = (kt + 1) * 64;
            float* Kd = (kt & 1) ? Ks0 : Ks1;
            float* Vd = (kt & 1) ? Vs0 : Vs1;
#pragma unroll
            for (int i = 0; i < 8; i++) {
                int key = i * 8 + kv_key;
                int kg  = nb + key;
                bool vd = kg < N1;
                const float* base = qkv_b + (size_t)(vd ? kg : 0) * H3 + h * 64 + kv_d0;
                cp16(smem_u32(&Kd[key * KSP + kv_d0]), base + 512,  vd);
                cp16(smem_u32(&Vd[key * VSP + kv_d0]), base + 1024, vd);
            }
            cp_commit();
        }

        // ---- S = Q K^T (b-frags shared across both m-tiles) ----
        float sacc[2][8][4];
#pragma unroll
        for (int mt = 0; mt < 2; mt++)
#pragma unroll
            for (int nt = 0; nt < 8; nt++)
#pragma unroll
                for (int q = 0; q < 4; q++) sacc[mt][nt][q] = 0.f;
#pragma unroll
        for (int kk = 0; kk < 8; kk++) {
#pragma unroll
            for (int nt = 0; nt < 8; nt++) {
                uint32_t b0 = __float_as_uint(Ksp[(nt * 8 + r) * KSP + kk * 8 + j    ]);
                uint32_t b1 = __float_as_uint(Ksp[(nt * 8 + r) * KSP + kk * 8 + j + 4]);
                mma8(sacc[0][nt], Qf[0][kk], b0, b1);
                mma8(sacc[1][nt], Qf[1][kk], b0, b1);
            }
        }

        // ---- scale (base-2) + mask ----
        if (kbase + 64 <= len1) {
#pragma unroll
            for (int mt = 0; mt < 2; mt++)
#pragma unroll
                for (int nt = 0; nt < 8; nt++)
#pragma unroll
                    for (int q = 0; q < 4; q++) sacc[mt][nt][q] *= ATT_SCALE_LOG2;
        } else {
#pragma unroll
            for (int mt = 0; mt < 2; mt++) {
#pragma unroll
                for (int nt = 0; nt < 8; nt++) {
#pragma unroll
                    for (int cc = 0; cc < 2; cc++) {
                        int kg = kbase + nt * 8 + 2 * j + cc;
                        bool kinv = (kg >= N1);
                        bool kpad = (kg >= len1);
                        sacc[mt][nt][cc]     = (kinv || (qpad[2 * mt]     && kpad)) ? -1e30f : sacc[mt][nt][cc]     * ATT_SCALE_LOG2;
                        sacc[mt][nt][2 + cc] = (kinv || (qpad[2 * mt + 1] && kpad)) ? -1e30f : sacc[mt][nt][2 + cc] * ATT_SCALE_LOG2;
                    }
                }
            }
        }

        // ---- online softmax (base-2, warp-local, 4 rows per lane) ----
        float fac[4];
#pragma unroll
        for (int mt = 0; mt < 2; mt++) {
            float mx0 = -1e30f, mx1 = -1e30f;
#pragma unroll
            for (int nt = 0; nt < 8; nt++) {
                mx0 = fmaxf(mx0, fmaxf(sacc[mt][nt][0], sacc[mt][nt][1]));
                mx1 = fmaxf(mx1, fmaxf(sacc[mt][nt][2], sacc[mt][nt][3]));
            }
            mx0 = fmaxf(mx0, __shfl_xor_sync(0xffffffffu, mx0, 1));
            mx0 = fmaxf(mx0, __shfl_xor_sync(0xffffffffu, mx0, 2));
            mx1 = fmaxf(mx1, __shfl_xor_sync(0xffffffffu, mx1, 1));
            mx1 = fmaxf(mx1, __shfl_xor_sync(0xffffffffu, mx1, 2));
            float mn0 = fmaxf(m[2 * mt],     mx0);
            float mn1 = fmaxf(m[2 * mt + 1], mx1);
            fac[2 * mt]     = exp2f(m[2 * mt]     - mn0);
            fac[2 * mt + 1] = exp2f(m[2 * mt + 1] - mn1);
            m[2 * mt] = mn0; m[2 * mt + 1] = mn1;
            float s0 = 0.f, s1 = 0.f;
#pragma unroll
            for (int nt = 0; nt < 8; nt++) {
#pragma unroll
                for (int cc = 0; cc < 2; cc++) {
                    float p0 = exp2f(sacc[mt][nt][cc]     - mn0);
                    float p1 = exp2f(sacc[mt][nt][2 + cc] - mn1);
                    sacc[mt][nt][cc] = p0;  sacc[mt][nt][2 + cc] = p1;
                    s0 += p0; s1 += p1;
                }
            }
            s0 += __shfl_xor_sync(0xffffffffu, s0, 1);
            s0 += __shfl_xor_sync(0xffffffffu, s0, 2);
            s1 += __shfl_xor_sync(0xffffffffu, s1, 1);
            s1 += __shfl_xor_sync(0xffffffffu, s1, 2);
            l[2 * mt]     = l[2 * mt]     * fac[2 * mt]     + s0;
            l[2 * mt + 1] = l[2 * mt + 1] * fac[2 * mt + 1] + s1;
        }
#pragma unroll
        for (int mt = 0; mt < 2; mt++)
#pragma unroll
            for (int nt = 0; nt < 8; nt++) {
                oacc[mt][nt][0] *= fac[2 * mt];     oacc[mt][nt][1] *= fac[2 * mt];
                oacc[mt][nt][2] *= fac[2 * mt + 1]; oacc[mt][nt][3] *= fac[2 * mt + 1];
            }

        // ---- P -> smem (own rows only), then PV ----
#pragma unroll
        for (int mt = 0; mt < 2; mt++) {
            const int brow = wq + mt * 16;
#pragma unroll
            for (int nt = 0; nt < 8; nt++) {
                *(float2*)&Ps[(brow + r    ) * ATP + nt * 8 + 2 * j] =
                    make_float2(sacc[mt][nt][0], sacc[mt][nt][1]);
                *(float2*)&Ps[(brow + r + 8) * ATP + nt * 8 + 2 * j] =
                    make_float2(sacc[mt][nt][2], sacc[mt][nt][3]);
            }
        }
        __syncwarp();

#pragma unroll
        for (int kk = 0; kk < 8; kk++) {
            uint32_t af[2][4];
#pragma unroll
            for (int mt = 0; mt < 2; mt++) {
                const int brow = wq + mt * 16;
                af[mt][0] = __float_as_uint(Ps[(brow + r    ) * ATP + kk * 8 + j    ]);
                af[mt][1] = __float_as_uint(Ps[(brow + r + 8) * ATP + kk * 8 + j    ]);
                af[mt][2] = __float_as_uint(Ps[(brow + r    ) * ATP + kk * 8 + j + 4]);
                af[mt][3] = __float_as_uint(Ps[(brow + r + 8) * ATP + kk * 8 + j + 4]);
            }
#pragma unroll
            for (int nt = 0; nt < 8; nt++) {
                uint32_t b0 = __float_as_uint(Vsp[(kk * 8 + j    ) * VSP + nt * 8 + r]);
                uint32_t b1 = __float_as_uint(Vsp[(kk * 8 + j + 4) * VSP + nt * 8 + r]);
                mma8(oacc[0][nt], af[0], b0, b1);
                mma8(oacc[1][nt], af[1], b0, b1);
            }
        }
    }

    // ---- normalize + write O ----
    float inv[4];
#pragma unroll
    for (int q = 0; q < 4; q++) inv[q] = 1.f / l[q];
    float* ob = o + (size_t)b * N1 * DIM + h * 64;
#pragma unroll
    for (int mt = 0; mt < 2; mt++) {
#pragma unroll
        for (int half = 0; half < 2; half++) {
            int rg = rowg[2 * mt + half];
            if (rg >= N1) continue;
            float sc = inv[2 * mt + half];
#pragma unroll
            for (int nt = 0; nt < 8; nt++)
                *(float2*)&ob[(size_t)rg * DIM + nt * 8 + 2 * j] =
                    make_float2(oacc[mt][nt][half * 2 + 0] * sc,
                                oacc[mt][nt][half * 2 + 1] * sc);
        }
    }
}

// ---------------- final LN + classifier head (cls token only) ----------------
__global__ __launch_bounds__(256) void head_kernel(
    const float* __restrict__ x, const float* __restrict__ g,
    const float* __restrict__ bb, const float* __restrict__ hw,
    const float* __restrict__ hb, float* __restrict__ out)
{
    const int b = blockIdx.x;
    const float* xr = x + (size_t)b * N1 * DIM;
    float v[2];
    float s = 0.f, s2 = 0.f;
#pragma unroll
    for (int it = 0; it < 2; it++) {
        v[it] = xr[threadIdx.x + it * 256];
        s += v[it]; s2 += v[it] * v[it];
    }
#pragma unroll
    for (int off = 16; off; off >>= 1) {
        s  += __shfl_xor_sync(0xffffffffu, s,  off);
        s2 += __shfl_xor_sync(0xffffffffu, s2, off);
    }
    __shared__ float rs[8], rs2[8];
    __shared__ float smean, srstd;
    const int w = threadIdx.x >> 5;
    if ((threadIdx.x & 31) == 0) { rs[w] = s; rs2[w] = s2; }
    __syncthreads();
    if (threadIdx.x == 0) {
        float a = 0.f, a2 = 0.f;
        for (int i = 0; i < 8; i++) { a += rs[i]; a2 += rs2[i]; }
        float mean = a * (1.f / DIM);
        float var  = a2 * (1.f / DIM) - mean * mean;
        smean = mean;
        srstd = rsqrtf(var + 1e-5f);
    }
    __syncthreads();
    const float mean = smean, rstd = srstd;

    float d0 = 0.f, d1 = 0.f;
#pragma unroll
    for (int it = 0; it < 2; it++) {
        int c = threadIdx.x + it * 256;
        float xn = (v[it] - mean) * rstd * g[c] + bb[c];
        d0 += xn * hw[2 * c + 0];
        d1 += xn * hw[2 * c + 1];
    }
#pragma unroll
    for (int off = 16; off; off >>= 1) {
        d0 += __shfl_xor_sync(0xffffffffu, d0, off);
        d1 += __shfl_xor_sync(0xffffffffu, d1, off);
    }
    __syncthreads();
    if ((threadIdx.x & 31) == 0) { rs[w] = d0; rs2[w] = d1; }
    __syncthreads();
    if (threadIdx.x == 0) {
        float a0 = 0.f, a1 = 0.f;
        for (int i = 0; i < 8; i++) { a0 += rs[i]; a1 += rs2[i]; }
        out[b * 2 + 0] = a0 + hb[0];
        out[b * 2 + 1] = a1 + hb[1];
    }
}

// ---------------- launch ----------------
extern "C" void kernel_launch(void* const* d_in, const int* in_sizes, int n_in,
                              void* d_out, int out_size)
{
    const float* x      = (const float*)d_in[0];
    const int*   lens   = (const int*)  d_in[1];
    const float* cls    = (const float*)d_in[2];
    const float* fc_w   = (const float*)d_in[3];
    const float* fc_b   = (const float*)d_in[4];
    const float* ln1_g  = (const float*)d_in[5];
    const float* ln1_b  = (const float*)d_in[6];
    const float* qkv_w  = (const float*)d_in[7];
    const float* out_w  = (const float*)d_in[8];
    const float* out_b  = (const float*)d_in[9];
    const float* ln2_g  = (const float*)d_in[10];
    const float* ln2_b  = (const float*)d_in[11];
    const float* ff1_w  = (const float*)d_in[12];
    const float* ff1_b  = (const float*)d_in[13];
    const float* ff2_w  = (const float*)d_in[14];
    const float* ff2_b  = (const float*)d_in[15];
    const float* lnf_g  = (const float*)d_in[16];
    const float* lnf_b  = (const float*)d_in[17];
    const float* head_w = (const float*)d_in[18];
    const float* head_b = (const float*)d_in[19];
    float* out = (float*)d_out;

    float *gx, *gxn, *gqkv, *go, *gh;
    cudaGetSymbolAddress((void**)&gx,   g_x);
    cudaGetSymbolAddress((void**)&gxn,  g_xn);
    cudaGetSymbolAddress((void**)&gqkv, g_qkv);
    cudaGetSymbolAddress((void**)&go,   g_o);
    cudaGetSymbolAddress((void**)&gh,   g_h);

    cudaFuncSetAttribute(sgemm_tf32, cudaFuncAttributeMaxDynamicSharedMemorySize, GEMM_SMEM);
    cudaFuncSetAttribute(attn_tf32,  cudaFuncAttributeMaxDynamicSharedMemorySize, ATT_SMEM);

    // cls rows
    cls_fill_kernel<<<BATCH, DIM>>>(cls, gx);

    // fc + GELU, remapped into cls-offset layout: M=8192, N=512, K=768
    sgemm_tf32<<<dim3(DIM / BN, (BATCH * NTOK + BM - 1) / BM), 256, GEMM_SMEM>>>(
        x, fc_w, fc_b, nullptr, gx, BATCH * NTOK, DIM, DIN, /*mode=*/2, /*remap=*/1);

    const int gy = (ROWS_TOT + BM - 1) / BM;   // 65
    for (int l = 0; l < DEPTH; l++) {
        ln_kernel<<<ROWS_TOT, 256>>>(gx, ln1_g + l * DIM, ln1_b + l * DIM, gxn);
        sgemm_tf32<<<dim3(H3 / BN, gy), 256, GEMM_SMEM>>>(
            gxn, qkv_w + (size_t)l * DIM * H3, nullptr, nullptr, gqkv,
            ROWS_TOT, H3, DIM, 0, 0);
        attn_tf32<<<dim3((N1 + 127) / 128, 8, BATCH), 128, ATT_SMEM>>>(gqkv, lens, go);
        sgemm_tf32<<<dim3(DIM / BN, gy), 256, GEMM_SMEM>>>(
            go, out_w + (size_t)l * DIM * DIM, out_b + l * DIM, gx, gx,
            ROWS_TOT, DIM, DIM, 3, 0);
        ln_kernel<<<ROWS_TOT, 256>>>(gx, ln2_g + l * DIM, ln2_b + l * DIM, gxn);
        sgemm_tf32<<<dim3(DIM / BN, gy), 256, GEMM_SMEM>>>(
            gxn, ff1_w + (size_t)l * DIM * DIM, ff1_b + l * DIM, nullptr, gh,
            ROWS_TOT, DIM, DIM, 2, 0);
        sgemm_tf32<<<dim3(DIM / BN, gy), 256, GEMM_SMEM>>>(
            gh, ff2_w + (size_t)l * DIM * DIM, ff2_b + l * DIM, gx, gx,
            ROWS_TOT, DIM, DIM, 3, 0);
    }

    head_kernel<<<BATCH, 256>>>(gx, lnf_g, lnf_b, head_w, head_b, out);
}